// round 8
// baseline (speedup 1.0000x reference)
#include <cuda_runtime.h>

#define HIDDEN    128
#define MAX_NODES 100000
#define NCOMBINE_BLOCKS 33     // 33 * 8 warps = 264 >= 258 combine tasks
#define NFLAGS 148

// Scratch (device globals; allocation is forbidden).
// Gap form: softmax over 2 classes depends only on l0-l1, so per node keep
//   gs[n] = n·dA,  gd[n] = n·dB,  dA/dB = W1 halves @ (w2_0 - w2_1).
__device__ float  g_GS[MAX_NODES];
__device__ float  g_GD[MAX_NODES];
__device__ float4 g_dAv[32], g_dBv[32];   // dA, dB as 32 x float4
__device__ float  g_gapb;                 // b1·(w2_0-w2_1) + b2_0 - b2_1
__device__ int    g_is64;
__device__ int    g_done = 0;             // combine-block completion counter
// Flag mirrored across 148 cache lines so pollers spread over LTS slices.
__device__ int    g_flags[NFLAGS * 32];   // stride 32 ints = 128B per flag

// ---------------------------------------------------------------------------
// Fused kernel.
//  Phase A (blocks 0..32): collapse layers into the gap direction
//    dA[i] = sum_k W1[i][k]     * (W2[k][0]-W2[k][1])   i in [0,128)
//    dB[i] = sum_k W1[128+i][k] * (W2[k][0]-W2[k][1])
//    + gap bias + warp-parallel edge-dtype probe. Last block mirrors the
//    release flag to 148 lines.
//  Phase B (all blocks): prefetch 8 feature rows per warp into registers
//    (HBM stream starts immediately), tid0-only poll on this block's flag
//    line, then per-node dot products + warp reduction.
// ---------------------------------------------------------------------------
#define NODES_PER_WARP  8
#define WARPS_PER_BLOCK 8
#define NODES_PER_BLOCK (NODES_PER_WARP * WARPS_PER_BLOCK)   // 64

__global__ void __launch_bounds__(256) fused_kernel(
        const float* __restrict__ feat,
        const float* __restrict__ W1, const float* __restrict__ b1,
        const float* __restrict__ W2, const float* __restrict__ b2,
        const long long* __restrict__ edges_as_i64,
        int n_edges, int n_nodes)
{
    int tid  = threadIdx.x;
    int warp = tid >> 5;
    int lane = tid & 31;

    // ---- Phase A: combine (low-bid blocks only; always wave-1) ----
    if (blockIdx.x < NCOMBINE_BLOCKS) {
        int gw = blockIdx.x * WARPS_PER_BLOCK + warp;
        if (gw < 256) {
            int i = gw;
            float acc = 0.f;
            #pragma unroll
            for (int k = lane; k < 4 * HIDDEN; k += 32)
                acc += W1[i * (4 * HIDDEN) + k] * (W2[2 * k] - W2[2 * k + 1]);
            #pragma unroll
            for (int o = 16; o; o >>= 1) acc += __shfl_xor_sync(0xffffffffu, acc, o);
            if (lane == 0) {
                float* dst = (i < HIDDEN) ? (float*)g_dAv : (float*)g_dBv;
                dst[i & (HIDDEN - 1)] = acc;
            }
        } else if (gw == 256) {
            float acc = 0.f;
            #pragma unroll
            for (int k = lane; k < 4 * HIDDEN; k += 32)
                acc += b1[k] * (W2[2 * k] - W2[2 * k + 1]);
            #pragma unroll
            for (int o = 16; o; o >>= 1) acc += __shfl_xor_sync(0xffffffffu, acc, o);
            if (lane == 0) g_gapb = acc + b2[0] - b2[1];
        } else if (gw == 257) {
            // Dtype probe: int32 data misread as int64 pairs fails the
            // [0, MAX_NODES) range check almost surely over 64 samples.
            int ok = 1;
            #pragma unroll
            for (int r = 0; r < 2; ++r) {
                int t = r * 32 + lane;
                if (t < n_edges) {
                    long long v = edges_as_i64[t];
                    if (v < 0 || v >= (long long)MAX_NODES) ok = 0;
                }
            }
            ok = __all_sync(0xffffffffu, ok);
            if (lane == 0) g_is64 = ok;
        }
        __syncthreads();
        if (tid == 0) {
            __threadfence();                       // publish weights/bias/probe
            if (atomicAdd(&g_done, 1) == NCOMBINE_BLOCKS - 1) {
                // Release: mirror flag across 148 separate cache lines.
                #pragma unroll 4
                for (int f = 0; f < NFLAGS; ++f)
                    *(volatile int*)&g_flags[f * 32] = 1;
            }
        }
    }

    // ---- Phase B: node projections ----
    int node0 = blockIdx.x * NODES_PER_BLOCK + warp * NODES_PER_WARP;

    // Prefetch feature rows BEFORE waiting: HBM stream starts at t=0.
    float4 x[NODES_PER_WARP];
    #pragma unroll
    for (int r = 0; r < NODES_PER_WARP; ++r) {
        int node = node0 + r;
        if (node < n_nodes)
            x[r] = reinterpret_cast<const float4*>(feat + (size_t)node * HIDDEN)[lane];
    }

    // tid0-only wait on this block's private flag line.
    if (tid == 0) {
        volatile int* f = &g_flags[(blockIdx.x % NFLAGS) * 32];
        while (*f == 0) __nanosleep(128);
        __threadfence();                           // acquire
    }
    __syncthreads();

    float4 wa = g_dAv[lane];
    float4 wb = g_dBv[lane];

    #pragma unroll
    for (int r = 0; r < NODES_PER_WARP; ++r) {
        int node = node0 + r;
        if (node >= n_nodes) break;
        float gs = x[r].x * wa.x + x[r].y * wa.y + x[r].z * wa.z + x[r].w * wa.w;
        float gd = x[r].x * wb.x + x[r].y * wb.y + x[r].z * wb.z + x[r].w * wb.w;
        #pragma unroll
        for (int o = 16; o; o >>= 1) {
            gs += __shfl_xor_sync(0xffffffffu, gs, o);
            gd += __shfl_xor_sync(0xffffffffu, gd, o);
        }
        if (lane == 0) {
            g_GS[node] = gs;
            g_GD[node] = gd;
        }
    }
}

// ---------------------------------------------------------------------------
// Edge kernel: 4 edges per thread; 4-byte gathers from two 400 KB
// L2-resident tables (8 independent LDG.32 in flight per thread).
//   gap = gs[s] + gd[d] + gapb = l0 - l1;  p1 = 1/(1+exp(gap))
// Also resets the fused kernel's sync state for the next graph replay
// (this kernel runs strictly after, and before the next replay).
// ---------------------------------------------------------------------------
#define EDGES_PER_THREAD 4

__global__ void __launch_bounds__(256) edge_kernel(const void* __restrict__ edges,
                                                   float2* __restrict__ out,
                                                   int n_edges)
{
    if (blockIdx.x == 0) {
        if (threadIdx.x < NFLAGS) g_flags[threadIdx.x * 32] = 0;
        if (threadIdx.x == 255) g_done = 0;
    }

    int t = blockIdx.x * blockDim.x + threadIdx.x;
    int base = t * EDGES_PER_THREAD;
    if (base >= n_edges) return;

    float gapb = g_gapb;
    int is64 = g_is64;

    int s[EDGES_PER_THREAD], d[EDGES_PER_THREAD];

    if (base + EDGES_PER_THREAD <= n_edges) {
        if (is64) {
            const longlong2* E = (const longlong2*)edges;
            longlong2 s01 = E[(base >> 1)];
            longlong2 s23 = E[(base >> 1) + 1];
            longlong2 d01 = E[((n_edges + base) >> 1)];
            longlong2 d23 = E[((n_edges + base) >> 1) + 1];
            s[0] = (int)s01.x; s[1] = (int)s01.y; s[2] = (int)s23.x; s[3] = (int)s23.y;
            d[0] = (int)d01.x; d[1] = (int)d01.y; d[2] = (int)d23.x; d[3] = (int)d23.y;
        } else {
            const int4* E = (const int4*)edges;
            int4 sv = E[base >> 2];
            int4 dv = E[(n_edges + base) >> 2];
            s[0] = sv.x; s[1] = sv.y; s[2] = sv.z; s[3] = sv.w;
            d[0] = dv.x; d[1] = dv.y; d[2] = dv.z; d[3] = dv.w;
        }

        float gs[EDGES_PER_THREAD], gd[EDGES_PER_THREAD];
        #pragma unroll
        for (int r = 0; r < EDGES_PER_THREAD; ++r) gs[r] = __ldg(&g_GS[s[r]]);
        #pragma unroll
        for (int r = 0; r < EDGES_PER_THREAD; ++r) gd[r] = __ldg(&g_GD[d[r]]);

        float p1[EDGES_PER_THREAD];
        #pragma unroll
        for (int r = 0; r < EDGES_PER_THREAD; ++r)
            p1[r] = 1.0f / (1.0f + __expf(gs[r] + gd[r] + gapb));

        float4* o4 = (float4*)(out + base);   // base % 4 == 0 -> 32B aligned
        o4[0] = make_float4(1.0f - p1[0], p1[0], 1.0f - p1[1], p1[1]);
        o4[1] = make_float4(1.0f - p1[2], p1[2], 1.0f - p1[3], p1[3]);
    } else {
        for (int e = base; e < n_edges; ++e) {
            int si, di;
            if (is64) {
                const long long* E = (const long long*)edges;
                si = (int)E[e]; di = (int)E[e + n_edges];
            } else {
                const int* E = (const int*)edges;
                si = E[e]; di = E[e + n_edges];
            }
            float p = 1.0f / (1.0f + __expf(__ldg(&g_GS[si]) + __ldg(&g_GD[di]) + gapb));
            out[e] = make_float2(1.0f - p, p);
        }
    }
}

// ---------------------------------------------------------------------------
// Launch. metadata order:
//   0: node_features_after_gcn (float32, N_NODES*128)
//   1: edges                   (int64 or int32, 2*N_EDGES)
//   2: W1 (256*512)  3: b1 (512)  4: W2 (512*2)  5: b2 (2)
// ---------------------------------------------------------------------------
extern "C" void kernel_launch(void* const* d_in, const int* in_sizes, int n_in,
                              void* d_out, int out_size)
{
    const float* feat  = (const float*)d_in[0];
    const void*  edges = d_in[1];
    const float* W1    = (const float*)d_in[2];
    const float* b1    = (const float*)d_in[3];
    const float* W2    = (const float*)d_in[4];
    const float* b2    = (const float*)d_in[5];

    int n_nodes = in_sizes[0] / HIDDEN;
    if (n_nodes > MAX_NODES) n_nodes = MAX_NODES;
    int n_edges = in_sizes[1] / 2;

    int nblocks = (n_nodes + NODES_PER_BLOCK - 1) / NODES_PER_BLOCK;
    if (nblocks < NCOMBINE_BLOCKS) nblocks = NCOMBINE_BLOCKS;

    fused_kernel<<<nblocks, 256>>>(feat, W1, b1, W2, b2,
                                   (const long long*)edges, n_edges, n_nodes);

    int nthreads = (n_edges + EDGES_PER_THREAD - 1) / EDGES_PER_THREAD;
    edge_kernel<<<(nthreads + 255) / 256, 256>>>(edges, (float2*)d_out, n_edges);
}

// round 10
// speedup vs baseline: 1.0982x; 1.0982x over previous
#include <cuda_runtime.h>

#define HIDDEN    128
#define MAX_NODES 100000

// Scratch (device globals; allocation is forbidden).
// Gap form: softmax over 2 classes depends only on l0-l1, so per node keep
//   gs[n] = n·dA,  gd[n] = n·dB,  dA/dB = W1 halves @ (w2_0 - w2_1).
__device__ float  g_GS[MAX_NODES];
__device__ float  g_GD[MAX_NODES];
__device__ float4 g_dAv[32], g_dBv[32];   // dA, dB as 32 x float4
__device__ float  g_gapb;                 // b1·(w2_0-w2_1) + b2_0 - b2_1
__device__ int    g_is64;

// ---------------------------------------------------------------------------
// Kernel A: collapse both layers into the gap direction. BLOCK-PER-ROW for
// maximum memory parallelism at tiny size (258 blocks x 256 threads; each
// thread loads 2 of the row's 512 elements, then block-reduce).
//   dA[i] = sum_k W1[i][k]     * (W2[k][0]-W2[k][1])   i in [0,128)
//   dB[i] = sum_k W1[128+i][k] * (W2[k][0]-W2[k][1])
//   block 256: gap bias;  block 257: edge dtype probe.
// ---------------------------------------------------------------------------
__global__ void __launch_bounds__(256) combine_kernel(
        const float* __restrict__ W1, const float* __restrict__ b1,
        const float* __restrict__ W2, const float* __restrict__ b2,
        const long long* __restrict__ edges_as_i64, int n_edges)
{
    __shared__ float red[8];
    int b    = blockIdx.x;
    int tid  = threadIdx.x;
    int warp = tid >> 5;
    int lane = tid & 31;

    if (b < 257) {
        // w2 gap direction for this thread's two k positions (4 KB, L2-hot).
        float w0 = W2[2 * tid]           - W2[2 * tid + 1];
        float w1 = W2[2 * (tid + 256)]   - W2[2 * (tid + 256) + 1];
        const float* row = (b < 256) ? (W1 + (size_t)b * (4 * HIDDEN)) : b1;
        float acc = row[tid] * w0 + row[tid + 256] * w1;

        #pragma unroll
        for (int o = 16; o; o >>= 1) acc += __shfl_xor_sync(0xffffffffu, acc, o);
        if (lane == 0) red[warp] = acc;
        __syncthreads();
        if (warp == 0) {
            float v = (lane < 8) ? red[lane] : 0.f;
            #pragma unroll
            for (int o = 4; o; o >>= 1) v += __shfl_xor_sync(0xffffffffu, v, o);
            if (lane == 0) {
                if (b < HIDDEN)       ((float*)g_dAv)[b] = v;
                else if (b < 256)     ((float*)g_dBv)[b - HIDDEN] = v;
                else                  g_gapb = v + b2[0] - b2[1];
            }
        }
    } else if (warp == 0) {
        // Warp-parallel dtype probe: an int32 buffer misread as int64 pairs
        // fails the [0, MAX_NODES) range check almost surely over 64 samples.
        int ok = 1;
        #pragma unroll
        for (int r = 0; r < 2; ++r) {
            int t = r * 32 + lane;
            if (t < n_edges) {
                long long v = edges_as_i64[t];
                if (v < 0 || v >= (long long)MAX_NODES) ok = 0;
            }
        }
        ok = __all_sync(0xffffffffu, ok);
        if (lane == 0) g_is64 = ok;
    }
}

// ---------------------------------------------------------------------------
// Kernel B: per-node gap projections. 8 nodes per warp, all row loads
// front-batched (MLP_p1=8). Streams 51.2 MB of features once (HBM floor).
// ---------------------------------------------------------------------------
#define NODES_PER_WARP  8
#define WARPS_PER_BLOCK 8
#define NODES_PER_BLOCK (NODES_PER_WARP * WARPS_PER_BLOCK)   // 64

__global__ void __launch_bounds__(256) node_kernel(const float* __restrict__ feat,
                                                   int n_nodes)
{
    int warp = threadIdx.x >> 5;
    int lane = threadIdx.x & 31;
    int node0 = blockIdx.x * NODES_PER_BLOCK + warp * NODES_PER_WARP;

    float4 x[NODES_PER_WARP];
    #pragma unroll
    for (int r = 0; r < NODES_PER_WARP; ++r) {
        int node = node0 + r;
        if (node < n_nodes)
            x[r] = reinterpret_cast<const float4*>(feat + (size_t)node * HIDDEN)[lane];
    }

    float4 wa = g_dAv[lane];
    float4 wb = g_dBv[lane];

    #pragma unroll
    for (int r = 0; r < NODES_PER_WARP; ++r) {
        int node = node0 + r;
        if (node >= n_nodes) break;
        float gs = x[r].x * wa.x + x[r].y * wa.y + x[r].z * wa.z + x[r].w * wa.w;
        float gd = x[r].x * wb.x + x[r].y * wb.y + x[r].z * wb.z + x[r].w * wb.w;
        #pragma unroll
        for (int o = 16; o; o >>= 1) {
            gs += __shfl_xor_sync(0xffffffffu, gs, o);
            gd += __shfl_xor_sync(0xffffffffu, gd, o);
        }
        if (lane == 0) {
            g_GS[node] = gs;
            g_GD[node] = gd;
        }
    }
}

// ---------------------------------------------------------------------------
// Kernel C: 2 edges per thread (grid ~977 -> high occupancy to cover L2
// gather latency). 4-byte gathers from two 400 KB L2-resident tables.
//   gap = gs[s] + gd[d] + gapb = l0 - l1;  p1 = 1/(1+exp(gap))
// ---------------------------------------------------------------------------
__global__ void __launch_bounds__(256) edge_kernel(const void* __restrict__ edges,
                                                   float2* __restrict__ out,
                                                   int n_edges)
{
    int t = blockIdx.x * blockDim.x + threadIdx.x;
    int base = t * 2;
    if (base >= n_edges) return;

    float gapb = g_gapb;

    if (base + 2 <= n_edges) {
        int s0, s1, d0, d1;
        if (g_is64) {
            const longlong2* E = (const longlong2*)edges;
            longlong2 s = E[base >> 1];                 // edges[base], [base+1]
            longlong2 d = E[(n_edges + base) >> 1];     // n_edges even here
            s0 = (int)s.x; s1 = (int)s.y; d0 = (int)d.x; d1 = (int)d.y;
        } else {
            const int2* E = (const int2*)edges;
            int2 s = E[base >> 1];
            int2 d = E[(n_edges + base) >> 1];
            s0 = s.x; s1 = s.y; d0 = d.x; d1 = d.y;
        }

        float gs0 = __ldg(&g_GS[s0]);
        float gs1 = __ldg(&g_GS[s1]);
        float gd0 = __ldg(&g_GD[d0]);
        float gd1 = __ldg(&g_GD[d1]);

        float p0 = 1.0f / (1.0f + __expf(gs0 + gd0 + gapb));
        float p1 = 1.0f / (1.0f + __expf(gs1 + gd1 + gapb));

        // base even -> out+base is 16B aligned
        *(float4*)(out + base) = make_float4(1.0f - p0, p0, 1.0f - p1, p1);
    } else {
        // odd tail: last edge
        int e = n_edges - 1;
        int si, di;
        if (g_is64) {
            const long long* E = (const long long*)edges;
            si = (int)E[e]; di = (int)E[e + n_edges];
        } else {
            const int* E = (const int*)edges;
            si = E[e]; di = E[e + n_edges];
        }
        float p = 1.0f / (1.0f + __expf(__ldg(&g_GS[si]) + __ldg(&g_GD[di]) + gapb));
        out[e] = make_float2(1.0f - p, p);
    }
}

// ---------------------------------------------------------------------------
// Launch. metadata order:
//   0: node_features_after_gcn (float32, N_NODES*128)
//   1: edges                   (int64 or int32, 2*N_EDGES)
//   2: W1 (256*512)  3: b1 (512)  4: W2 (512*2)  5: b2 (2)
// ---------------------------------------------------------------------------
extern "C" void kernel_launch(void* const* d_in, const int* in_sizes, int n_in,
                              void* d_out, int out_size)
{
    const float* feat  = (const float*)d_in[0];
    const void*  edges = d_in[1];
    const float* W1    = (const float*)d_in[2];
    const float* b1    = (const float*)d_in[3];
    const float* W2    = (const float*)d_in[4];
    const float* b2    = (const float*)d_in[5];

    int n_nodes = in_sizes[0] / HIDDEN;
    if (n_nodes > MAX_NODES) n_nodes = MAX_NODES;
    int n_edges = in_sizes[1] / 2;

    // A: block-per-row, 258 blocks.
    combine_kernel<<<258, 256>>>(W1, b1, W2, b2, (const long long*)edges, n_edges);

    // B: 64 nodes per block.
    node_kernel<<<(n_nodes + NODES_PER_BLOCK - 1) / NODES_PER_BLOCK, 256>>>(feat, n_nodes);

    // C: 2 edges per thread.
    int nthreads = (n_edges + 1) / 2;
    edge_kernel<<<(nthreads + 255) / 256, 256>>>(edges, (float2*)d_out, n_edges);
}